// round 4
// baseline (speedup 1.0000x reference)
#include <cuda_runtime.h>

// QuantumLayer_9483287790225 — analytic closed form (R0 derivation).
//
//   z_i = cos(pi*x_i) * ( cos(w_i) - sin(w_i)*sin(pi*x_i) )
//   <Z_0> = z_1*...*z_13 ;  <Z_j> = z_0*...*z_j  (j>=1)
//
// R3: 8 lanes per batch, 2 wires per lane (float2 loads/stores, rows are
// 8B-aligned: 14 floats = 56B stride). Lane L computes z_{2L}, z_{2L+1};
// q_L = z_{2L}*z_{2L+1} except lane 0 drops z_0 and lane 7 pads with 1.
// 3-step inclusive shfl product scan gives I_L = z_1..z_{2L+1};
// exclusive E_L = shfl_up(I,1). Outputs:
//   out[0]      = I_7 (= z_1..z_13, lane-7 broadcast)
//   out[2L]     = z_0 * E_L * z_{2L}          (L>=1)
//   out[2L+1]   = z_0 * E_L * z_{2L} * z_{2L+1}

#define NQ 14
#define BATCH 256
#define PI_F 3.14159265358979323846f

__global__ void __launch_bounds__(128, 1)
quantum_layer_kernel(const float* __restrict__ x,
                     const float* __restrict__ weight,
                     float* __restrict__ out)
{
    const unsigned tid = blockIdx.x * blockDim.x + threadIdx.x;
    const unsigned sub = tid & 7u;          // lane within 8-lane batch group
    const unsigned b   = tid >> 3;          // batch index

    // Each lane loads 2 wires. Lane 7 is padding (wires 14,15 don't exist).
    float2 xv = make_float2(0.0f, 0.0f);
    float2 wv = make_float2(0.0f, 0.0f);
    if (sub < 7u) {
        xv = *(const float2*)(x + b * NQ + 2 * sub);
        wv = *(const float2*)(weight + 2 * sub);
    }

    // z = cp * (cw - sw*sp), two independent wires -> MUFU ILP
    float aa = PI_F * xv.x, ab = PI_F * xv.y;
    float za = __cosf(aa) * (__cosf(wv.x) - __sinf(wv.x) * __sinf(aa));
    float zb = __cosf(ab) * (__cosf(wv.y) - __sinf(wv.y) * __sinf(ab));

    // Scan value: lane 0 excludes z_0; lane 7 contributes 1.
    float q = (sub == 0u) ? zb : za * zb;
    if (sub == 7u) q = 1.0f;

    // 3-step inclusive product scan over 8-lane groups.
    float I = q;
#pragma unroll
    for (int d = 1; d < 8; d <<= 1) {
        float t = __shfl_up_sync(0xffffffffu, I, d, 8);
        if (sub >= (unsigned)d) I *= t;
    }

    float E   = __shfl_up_sync(0xffffffffu, I, 1, 8);   // exclusive
    float z0  = __shfl_sync(0xffffffffu, za, 0, 8);
    float s13 = __shfl_sync(0xffffffffu, I, 7, 8);      // z_1..z_13

    if (sub < 7u) {
        float f  = (sub == 0u) ? z0 : z0 * E;           // z_0..z_{2L-1}
        float o0 = (sub == 0u) ? s13 : f * za;          // out[2L]
        float o1 = f * za * zb;                         // out[2L+1]... lane0: z0*za*zb? 
        // lane 0: out[1] = z0*z1 = z0*zb  (za == z0 itself, must not reuse)
        if (sub == 0u) o1 = z0 * zb;
        *(float2*)(out + b * NQ + 2 * sub) = make_float2(o0, o1);
    }
}

extern "C" void kernel_launch(void* const* d_in, const int* in_sizes, int n_in,
                              void* d_out, int out_size)
{
    const float* x      = (const float*)d_in[0];   // [256, 14]
    const float* weight = (const float*)d_in[1];   // [1, 14]
    float* out          = (float*)d_out;           // [256, 14]

    // 256 batches x 8 lanes = 2048 threads -> 16 blocks x 128.
    quantum_layer_kernel<<<16, 128>>>(x, weight, out);
}